// round 1
// baseline (speedup 1.0000x reference)
#include <cuda_runtime.h>
#include <cuda_bf16.h>

#define M_TOTAL 65536   // B*T = 512*128
#define C_DIM   384
#define H_DIM   64
#define T_DIM   128
#define B_DIM   512
#define SROW    68      // smem row stride (pad 64 -> 68): float4-aligned, conflict-free

// Scratch for Q, K, V planes: 3 * 65536 * 64 * 4B = 50.3 MB (static device array — allowed)
__device__ float g_qkv[3u * M_TOTAL * H_DIM];

// ---------------------------------------------------------------------------
// Kernel A: QKV projection GEMM. C[plane] = x @ W[plane]
// x: [65536, 384] row-major, W: [384, 64] row-major.
// Tile: BM=128, BN=64 (full H), BK=16; 256 threads; 8x4 register tile/thread.
// ---------------------------------------------------------------------------
__global__ __launch_bounds__(256) void qkv_gemm_kernel(
    const float* __restrict__ x,
    const float* __restrict__ Wq,
    const float* __restrict__ Wk,
    const float* __restrict__ Wv)
{
    constexpr int BM = 128, BN = 64, BK = 16;
    __shared__ float As[BK][BM + 4];   // transposed A tile, padded
    __shared__ float Bs[BK][BN];

    const int plane = blockIdx.y;
    const float* __restrict__ W = (plane == 0) ? Wq : (plane == 1) ? Wk : Wv;
    const int m0  = blockIdx.x * BM;
    const int tid = threadIdx.x;
    const int tx  = tid & 15;   // n: 4 outputs each -> 64
    const int ty  = tid >> 4;   // m: 8 outputs each -> 128

    float acc[8][4];
    #pragma unroll
    for (int i = 0; i < 8; i++)
        #pragma unroll
        for (int j = 0; j < 4; j++) acc[i][j] = 0.f;

    for (int k0 = 0; k0 < C_DIM; k0 += BK) {
        // Load A tile 128x16 (512 float4, 2 per thread), store transposed As[k][m]
        #pragma unroll
        for (int i = 0; i < 2; i++) {
            int idx = tid + i * 256;
            int r = idx >> 2;             // 0..127
            int c = (idx & 3) << 2;       // 0,4,8,12
            float4 a = *(const float4*)(x + (size_t)(m0 + r) * C_DIM + k0 + c);
            As[c + 0][r] = a.x;
            As[c + 1][r] = a.y;
            As[c + 2][r] = a.z;
            As[c + 3][r] = a.w;
        }
        // Load B tile 16x64 (256 float4, 1 per thread)
        {
            int r = tid >> 4;             // 0..15 (k)
            int c = (tid & 15) << 2;      // 0..60 (n)
            float4 bvec = *(const float4*)(W + (size_t)(k0 + r) * BN + c);
            *(float4*)&Bs[r][c] = bvec;
        }
        __syncthreads();

        #pragma unroll
        for (int k = 0; k < BK; k++) {
            float4 b4 = *(const float4*)&Bs[k][tx << 2];
            float4 a0 = *(const float4*)&As[k][ty << 3];
            float4 a1 = *(const float4*)&As[k][(ty << 3) + 4];
            float av[8] = {a0.x, a0.y, a0.z, a0.w, a1.x, a1.y, a1.z, a1.w};
            float bv[4] = {b4.x, b4.y, b4.z, b4.w};
            #pragma unroll
            for (int i = 0; i < 8; i++)
                #pragma unroll
                for (int j = 0; j < 4; j++)
                    acc[i][j] = fmaf(av[i], bv[j], acc[i][j]);
        }
        __syncthreads();
    }

    float* outp = g_qkv + (size_t)plane * M_TOTAL * H_DIM;
    #pragma unroll
    for (int i = 0; i < 8; i++) {
        int row = m0 + (ty << 3) + i;
        float4 v = make_float4(acc[i][0], acc[i][1], acc[i][2], acc[i][3]);
        *(float4*)(outp + (size_t)row * H_DIM + (tx << 2)) = v;
    }
}

// ---------------------------------------------------------------------------
// Kernel B: causal attention per batch.
// One CTA per batch (512 CTAs, 256 threads = 8 warps).
// smem: Q/K/V tiles [128][68] + per-warp weight rows [8][128].
// Each warp owns rows t = warp, warp+8, ...; lanes hold 4 score columns.
// ---------------------------------------------------------------------------
__global__ __launch_bounds__(256) void attn_kernel(float* __restrict__ out)
{
    extern __shared__ float sm[];
    float* Qs = sm;
    float* Ks = Qs + T_DIM * SROW;
    float* Vs = Ks + T_DIM * SROW;
    float* Wb = Vs + T_DIM * SROW;   // [8][128]

    const int b = blockIdx.x;
    const float* __restrict__ qg = g_qkv + (size_t)b * T_DIM * H_DIM;
    const float* __restrict__ kg = qg + (size_t)M_TOTAL * H_DIM;
    const float* __restrict__ vg = kg + (size_t)M_TOTAL * H_DIM;
    const int tid = threadIdx.x;

    // Stage Q, K, V into padded smem (float4 loads/stores; SROW%4==0 keeps alignment)
    for (int idx = tid; idx < (T_DIM * H_DIM) / 4; idx += 256) {
        int r = idx >> 4;
        int c = (idx & 15) << 2;
        *(float4*)(Qs + r * SROW + c) = *(const float4*)(qg + (size_t)r * H_DIM + c);
        *(float4*)(Ks + r * SROW + c) = *(const float4*)(kg + (size_t)r * H_DIM + c);
        *(float4*)(Vs + r * SROW + c) = *(const float4*)(vg + (size_t)r * H_DIM + c);
    }
    __syncthreads();

    const int warp = tid >> 5;
    const int lane = tid & 31;
    const float scale = 0.40824829046386301636f;   // 6^-0.5 (head_count scaling)

    for (int t = warp; t < T_DIM; t += 8) {
        const float* qrow = Qs + t * SROW;
        const float* kp0  = Ks + lane * SROW;

        // ---- scores: sc[j] = q[t] . k[lane + 32j] ----
        float sc[4] = {0.f, 0.f, 0.f, 0.f};
        #pragma unroll
        for (int h4 = 0; h4 < 16; h4++) {
            float4 qv = *(const float4*)(qrow + (h4 << 2));
            #pragma unroll
            for (int j = 0; j < 4; j++) {
                float4 kv = *(const float4*)(kp0 + j * 32 * SROW + (h4 << 2));
                sc[j] = fmaf(qv.x, kv.x, sc[j]);
                sc[j] = fmaf(qv.y, kv.y, sc[j]);
                sc[j] = fmaf(qv.z, kv.z, sc[j]);
                sc[j] = fmaf(qv.w, kv.w, sc[j]);
            }
        }
        #pragma unroll
        for (int j = 0; j < 4; j++) {
            int s = lane + (j << 5);
            sc[j] = (s <= t) ? sc[j] * scale : -1e30f;
        }

        // ---- softmax over the row (warp-wide) ----
        float mx = fmaxf(fmaxf(sc[0], sc[1]), fmaxf(sc[2], sc[3]));
        #pragma unroll
        for (int off = 16; off; off >>= 1)
            mx = fmaxf(mx, __shfl_xor_sync(0xffffffffu, mx, off));
        float e[4], ssum = 0.f;
        #pragma unroll
        for (int j = 0; j < 4; j++) { e[j] = __expf(sc[j] - mx); ssum += e[j]; }
        #pragma unroll
        for (int off = 16; off; off >>= 1)
            ssum += __shfl_xor_sync(0xffffffffu, ssum, off);
        float inv = __frcp_rn(ssum);

        float* wrow = Wb + (warp << 7);
        #pragma unroll
        for (int j = 0; j < 4; j++) wrow[lane + (j << 5)] = e[j] * inv;
        __syncwarp();

        // ---- out[t] = sum_{s<=t} w[s] * V[s] (lanes span h; 2 h each) ----
        float o0 = 0.f, o1 = 0.f;
        const float* vp = Vs + lane;
        for (int s = 0; s <= t; s++) {
            float w = wrow[s];
            o0 = fmaf(w, vp[s * SROW], o0);
            o1 = fmaf(w, vp[s * SROW + 32], o1);
        }
        float* op = out + (size_t)b * T_DIM * H_DIM + (size_t)t * H_DIM;
        op[lane]      = o0;
        op[lane + 32] = o1;
        __syncwarp();   // wrow write-after-read safety across t iterations
    }
}

// ---------------------------------------------------------------------------
extern "C" void kernel_launch(void* const* d_in, const int* in_sizes, int n_in,
                              void* d_out, int out_size)
{
    const float* x  = (const float*)d_in[0];
    const float* Wq = (const float*)d_in[1];
    const float* Wk = (const float*)d_in[2];
    const float* Wv = (const float*)d_in[3];
    float* out = (float*)d_out;

    dim3 g1(M_TOTAL / 128, 3);
    qkv_gemm_kernel<<<g1, 256>>>(x, Wq, Wk, Wv);

    int smem = (3 * T_DIM * SROW + 8 * T_DIM) * (int)sizeof(float);   // 108544 B
    cudaFuncSetAttribute(attn_kernel, cudaFuncAttributeMaxDynamicSharedMemorySize, smem);
    attn_kernel<<<B_DIM, 256, smem>>>(out);
}